// round 9
// baseline (speedup 1.0000x reference)
#include <cuda_runtime.h>
#include <math.h>

// ---------------------------------------------------------------------------
// SinkhornDistance: N=4, P1=P2=1024, D=16, EPS=0.1, MAX_ITER=100, THRESH=0.1
// Outputs (concatenated fp32): cost[4], pi[4*1024*1024], C[4*1024*1024]
// Round 9: R8 + symmetric 1-hop group barrier (one 128B flag line per group,
// every block's warp0 polls all 32 flags directly) + errSum/epoch publication
// moved off the critical warp (warp 15 of group leader block).
// ---------------------------------------------------------------------------

#define NB 4
#define P  1024
#define DD 16
#define EPSF 0.1f
#define KAP 14.426950408889634f        // log2(e)/eps
#define EPSLN2 0.06931471805599453f    // eps*ln2 = 1/KAP
#define MAX_ITER 100
#define THRESHF 0.1f
#define SBLOCKS 128
#define GBLK 32                        // blocks per batch group
#define STHREADS 512
#define PLANE (NB*P*P)

// ----------------------------- scratch (static device memory) ---------------
struct __align__(128) FlagLine { int f[GBLK]; };   // one L2 line per group
__device__ FlagLine g_flagsP[NB];
__device__ int      g_epoch[NB];         // last iteration published per group
__device__ float    g_errSum[NB][2];     // per-group err, ring by iter parity
__device__ float    g_CT[PLANE];         // transposed cost matrix (16 MB)
__device__ float    g_u[NB*P];           // kappa-scaled u
__device__ float    g_v[NB*P];           // kappa-scaled v
__device__ float    g_logmu[NB*P];
__device__ float    g_lognu[NB*P];
__device__ float    g_errPart[SBLOCKS];
__device__ float    g_rowPart[NB*P];

// ----------------------------- helpers --------------------------------------
__device__ __forceinline__ float ex2(float x) {
    float r; asm("ex2.approx.ftz.f32 %0, %1;" : "=f"(r) : "f"(x)); return r;
}
__device__ __forceinline__ float lg2(float x) {
    float r; asm("lg2.approx.ftz.f32 %0, %1;" : "=f"(r) : "f"(x)); return r;
}
__device__ __forceinline__ int ld_acq(const int* p) {
    int v; asm volatile("ld.acquire.gpu.s32 %0, [%1];" : "=r"(v) : "l"(p)); return v;
}
__device__ __forceinline__ void st_rel(int* p, int v) {
    asm volatile("st.release.gpu.s32 [%0], %1;" :: "l"(p), "r"(v));
}

// Symmetric 1-hop group barrier: block bb releases flag[bb]; warp0 of EVERY
// block polls the whole 128B flag line (lane L -> flag L). No leader hop.
__device__ __forceinline__ void gbar(int n, int bb, int epoch) {
    __syncthreads();
    if (threadIdx.x < 32) {
        if (threadIdx.x == 0) st_rel(&g_flagsP[n].f[bb], epoch);
        bool ok;
        do { ok = ld_acq(&g_flagsP[n].f[threadIdx.x]) >= epoch; }
        while (!__all_sync(0xffffffffu, ok));
    }
    __syncthreads();
}

// warp LSE merge of two (m,s) chunks (log2-domain, kappa-scaled)
__device__ __forceinline__ float lse_merge_butterfly(float m1, float s1,
                                                     float m2, float s2) {
    float M = fmaxf(m1, m2);
    float S = s1 * ex2(m1 - M) + s2 * ex2(m2 - M);
#pragma unroll
    for (int o = 16; o; o >>= 1) S += __shfl_xor_sync(0xffffffffu, S, o);
    return M + lg2(S);
}

// ----------------------------- kernel 0: init -------------------------------
__global__ void k_init(const float* __restrict__ wx, const float* __restrict__ wy) {
    int i = blockIdx.x * blockDim.x + threadIdx.x;   // 4096 threads total
    g_v[i] = 0.f;
    g_u[i] = 0.f;
    g_logmu[i] = logf(wx[i] + 1e-8f);
    g_lognu[i] = logf(wy[i] + 1e-8f);
}

// ----------------------------- kernel 1: cost matrix C and CT ---------------
__global__ void k_cost(const float* __restrict__ x, const float* __restrict__ y,
                       float* __restrict__ C) {
    __shared__ float xs[32][17];
    __shared__ float ys[32][17];
    __shared__ float tile[32][33];
    int n = blockIdx.z, I = blockIdx.y, J = blockIdx.x;
    int tid = threadIdx.x;   // 256

    for (int e = tid; e < 32 * DD; e += 256)
        xs[e >> 4][e & 15] = x[((size_t)(n * P + I * 32 + (e >> 4))) * DD + (e & 15)];
    for (int e = tid; e < 32 * DD; e += 256)
        ys[e >> 4][e & 15] = y[((size_t)(n * P + J * 32 + (e >> 4))) * DD + (e & 15)];
    __syncthreads();

    int ii = tid >> 3;
    int j0 = (tid & 7) * 4;
#pragma unroll
    for (int q = 0; q < 4; ++q) {
        int jj = j0 + q;
        float s = 0.f;
#pragma unroll
        for (int d = 0; d < DD; ++d) s += fabsf(xs[ii][d] - ys[jj][d]);
        tile[ii][jj] = s;
    }
    __syncthreads();

    for (int e = tid; e < 1024; e += 256) {
        int r = e >> 5, c = e & 31;
        C[((size_t)(n * P + I * 32 + r)) * P + (J * 32 + c)]    = tile[r][c];
        g_CT[((size_t)(n * P + J * 32 + r)) * P + (I * 32 + c)] = tile[c][r];
    }
}

// ----------------------------- kernel 2: barrier state reset ----------------
__global__ void k_flags() {
    int i = threadIdx.x;   // 128
    ((int*)g_flagsP)[i] = 0;
    if (i < NB) g_epoch[i] = -1;
}

// ----------------------------- kernel 3: persistent Sinkhorn ----------------
// SMEM: tile[32][1024] (kappa*C rows) | shv[1024] staging | sdu[32]
__global__ void __launch_bounds__(STHREADS, 1)
k_sink(const float* __restrict__ C, float* __restrict__ pi) {
    extern __shared__ __align__(16) float smem[];
    float* tile = smem;                  // 32*1024
    float* shv  = smem + 32 * 1024;      // 1024 (kv, then ku)
    float* sdu  = shv + 1024;            // 32
    __shared__ int sdone;

    int tid = threadIdx.x;
    int w = tid >> 5, lane = tid & 31;   // 16 warps
    int b = blockIdx.x;
    int n = b >> 5, bb = b & 31;
    int r0 = (b << 5) + w;               // global rows of this warp
    int r1 = r0 + 16;
    int jc0 = (bb << 5) + w;             // columns of this warp (within batch)
    int jc1 = jc0 + 16;

    // ---- prologue: row tile (kappa*C), coalesced ----
    {
        const float4* src = (const float4*)(C + ((size_t)b << 15));
        float4* dst = (float4*)tile;
#pragma unroll
        for (int k = 0; k < 16; ++k) {
            float4 c = __ldcg(&src[tid + (k << 9)]);
            c.x *= KAP; c.y *= KAP; c.z *= KAP; c.w *= KAP;
            dst[tid + (k << 9)] = c;
        }
    }
    // ---- prologue: column registers (kappa*CT rows jc0, jc1), coalesced ----
    float ctreg[64];
    {
        const float* ct0 = g_CT + (((size_t)((n << 10) + jc0)) << 10);
        const float* ct1 = g_CT + (((size_t)((n << 10) + jc1)) << 10);
#pragma unroll
        for (int k = 0; k < 32; ++k) ctreg[k]      = __ldcg(&ct0[(k << 5) + lane]) * KAP;
#pragma unroll
        for (int k = 0; k < 32; ++k) ctreg[32 + k] = __ldcg(&ct1[(k << 5) + lane]) * KAP;
    }
    float lmu0 = g_logmu[r0], lmu1 = g_logmu[r1];
    float lnu0 = g_lognu[(n << 10) + jc0], lnu1 = g_lognu[(n << 10) + jc1];
    float up0 = 0.f, up1 = 0.f;          // previous raw u of own rows
    int ep = 1;
    __syncthreads();

    for (int it = 0; it < MAX_ITER; ++it) {
        // ---- stage kappa*v + lagged done check (warp0 lanes 0-3 parallel) ----
        shv[tid]       = __ldcg(&g_v[(n << 10) + tid]);
        shv[tid + 512] = __ldcg(&g_v[(n << 10) + tid + 512]);
        if (w == 0) {
            int d = 0;
            if (it > 0) {
                int need = it - 1;
                if (lane < 4) { while (ld_acq(&g_epoch[lane]) < need) { } }
                __syncwarp();
                float e = (lane < 4) ? __ldcg(&g_errSum[lane][need & 1]) : 0.f;
                e += __shfl_xor_sync(0xffffffffu, e, 1);
                e += __shfl_xor_sync(0xffffffffu, e, 2);
                e = __shfl_sync(0xffffffffu, e, 0);
                d = (e * 0.25f < THRESHF) ? 1 : 0;
            }
            if (lane == 0) sdone = d;
        }
        __syncthreads();                         // BAR1: shv + sdone
        if (sdone) break;

        // ---- u-phase: rows r0, r1 (tile rows w, w+16) ----
        {
            float u_new0, u_new1;
#pragma unroll
            for (int rr = 0; rr < 2; ++rr) {
                const float* trow = tile + (((rr << 4) + w) << 10);
                float t[16];
                float m1 = -3.0e38f;
#pragma unroll
                for (int k = 0; k < 4; ++k) {
                    int idx = (lane << 2) + (k << 7);
                    float4 c = *(const float4*)(trow + idx);
                    float4 v = *(const float4*)(shv + idx);
                    float a0 = v.x - c.x, a1 = v.y - c.y;
                    float a2 = v.z - c.z, a3 = v.w - c.w;
                    t[(k << 2) + 0] = a0; t[(k << 2) + 1] = a1;
                    t[(k << 2) + 2] = a2; t[(k << 2) + 3] = a3;
                    m1 = fmaxf(m1, fmaxf(fmaxf(a0, a1), fmaxf(a2, a3)));
                }
#pragma unroll
                for (int o = 16; o; o >>= 1) m1 = fmaxf(m1, __shfl_xor_sync(0xffffffffu, m1, o));
                float s1 = 0.f;
#pragma unroll
                for (int q = 0; q < 16; ++q) s1 += ex2(t[q] - m1);

                float m2 = -3.0e38f;
#pragma unroll
                for (int k = 4; k < 8; ++k) {
                    int idx = (lane << 2) + (k << 7);
                    float4 c = *(const float4*)(trow + idx);
                    float4 v = *(const float4*)(shv + idx);
                    float a0 = v.x - c.x, a1 = v.y - c.y;
                    float a2 = v.z - c.z, a3 = v.w - c.w;
                    t[((k - 4) << 2) + 0] = a0; t[((k - 4) << 2) + 1] = a1;
                    t[((k - 4) << 2) + 2] = a2; t[((k - 4) << 2) + 3] = a3;
                    m2 = fmaxf(m2, fmaxf(fmaxf(a0, a1), fmaxf(a2, a3)));
                }
#pragma unroll
                for (int o = 16; o; o >>= 1) m2 = fmaxf(m2, __shfl_xor_sync(0xffffffffu, m2, o));
                float s2 = 0.f;
#pragma unroll
                for (int q = 0; q < 16; ++q) s2 += ex2(t[q] - m2);

                float L = lse_merge_butterfly(m1, s1, m2, s2);
                float u_raw = EPSF * ((rr == 0) ? lmu0 : lmu1) - EPSLN2 * L;
                if (rr == 0) u_new0 = u_raw; else u_new1 = u_raw;
            }
            if (lane == 0) {
                sdu[w]      = fabsf(u_new0 - up0);
                sdu[w + 16] = fabsf(u_new1 - up1);
                __stcg(&g_u[r0], u_new0 * KAP);
                __stcg(&g_u[r1], u_new1 * KAP);
            }
            up0 = u_new0; up1 = u_new1;
        }
        __syncthreads();                         // BAR2: sdu + g_u stores ordered
        if (w == 0) {   // block error partial, fixed butterfly order
            float e = sdu[lane];
#pragma unroll
            for (int o = 16; o; o >>= 1) e += __shfl_xor_sync(0xffffffffu, e, o);
            if (lane == 0) __stcg(&g_errPart[b], e);
        }
        gbar(n, bb, ep++);                       // group: all g_u + errPart visible

        // ---- err(it) + epoch published by warp 15 of group leader block ----
        // (off the critical path: consumed only at iteration it+1's done check)
        if (bb == 0 && w == 15) {
            float e = __ldcg(&g_errPart[(n << 5) + lane]);
#pragma unroll
            for (int o = 16; o; o >>= 1) e += __shfl_xor_sync(0xffffffffu, e, o);
            if (lane == 0) {
                __stcg(&g_errSum[n][it & 1], e);
                st_rel(&g_epoch[n], it);
            }
        }

        // ---- stage kappa*u ----
        shv[tid]       = __ldcg(&g_u[(n << 10) + tid]);
        shv[tid + 512] = __ldcg(&g_u[(n << 10) + tid + 512]);
        __syncthreads();                         // BAR3: shv = kappa*u

        // ---- v-phase: columns jc0, jc1 from registers ----
#pragma unroll
        for (int cc = 0; cc < 2; ++cc) {
            int base = cc << 5;
            float t[16];
            float m1 = -3.0e38f;
#pragma unroll
            for (int k = 0; k < 16; ++k) {
                float a = shv[(k << 5) + lane] - ctreg[base + k];
                t[k] = a; m1 = fmaxf(m1, a);
            }
#pragma unroll
            for (int o = 16; o; o >>= 1) m1 = fmaxf(m1, __shfl_xor_sync(0xffffffffu, m1, o));
            float s1 = 0.f;
#pragma unroll
            for (int q = 0; q < 16; ++q) s1 += ex2(t[q] - m1);

            float m2 = -3.0e38f;
#pragma unroll
            for (int k = 16; k < 32; ++k) {
                float a = shv[(k << 5) + lane] - ctreg[base + k];
                t[k - 16] = a; m2 = fmaxf(m2, a);
            }
#pragma unroll
            for (int o = 16; o; o >>= 1) m2 = fmaxf(m2, __shfl_xor_sync(0xffffffffu, m2, o));
            float s2 = 0.f;
#pragma unroll
            for (int q = 0; q < 16; ++q) s2 += ex2(t[q] - m2);

            float L = lse_merge_butterfly(m1, s1, m2, s2);
            float v_raw = EPSF * ((cc == 0) ? lnu0 : lnu1) - EPSLN2 * L;
            if (lane == 0)
                __stcg(&g_v[(n << 10) + ((cc == 0) ? jc0 : jc1)], v_raw * KAP);
        }
        gbar(n, bb, ep++);                       // group: all g_v visible
    }

    // ---------------- epilogue: pi rows + per-row cost partial ----------------
    __syncthreads();
    shv[tid]       = __ldcg(&g_v[(n << 10) + tid]);        // kappa*v (fresh)
    shv[tid + 512] = __ldcg(&g_v[(n << 10) + tid + 512]);
    __syncthreads();
#pragma unroll
    for (int rr = 0; rr < 2; ++rr) {
        int rloc = (rr << 4) + w;
        int rg = (b << 5) + rloc;
        const float* trow = tile + (rloc << 10);
        float* prow = pi + ((size_t)rg << 10);
        float uk = ((rr == 0) ? up0 : up1) * KAP;
        float acc = 0.f;
#pragma unroll
        for (int k = 0; k < 8; ++k) {
            int idx = (lane << 2) + (k << 7);
            float4 c = *(const float4*)(trow + idx);
            float4 v = *(const float4*)(shv + idx);
            float4 p;
            p.x = ex2(uk + v.x - c.x);
            p.y = ex2(uk + v.y - c.y);
            p.z = ex2(uk + v.z - c.z);
            p.w = ex2(uk + v.w - c.w);
            __stcg((float4*)(prow + idx), p);
            acc += p.x * c.x + p.y * c.y + p.z * c.z + p.w * c.w;
        }
#pragma unroll
        for (int o = 16; o; o >>= 1) acc += __shfl_xor_sync(0xffffffffu, acc, o);
        if (lane == 0) __stcg(&g_rowPart[rg], acc * EPSLN2);   // undo kappa on C
    }
}

// ----------------------------- kernel 4: deterministic cost reduce ----------
__global__ void k_final(float* __restrict__ cost) {
    int tid = threadIdx.x;   // 128
    int n = tid >> 5, lane = tid & 31;
    float s = 0.f;
#pragma unroll
    for (int q = 0; q < 32; ++q) s += g_rowPart[(n << 10) + lane + (q << 5)];
#pragma unroll
    for (int o = 16; o; o >>= 1) s += __shfl_xor_sync(0xffffffffu, s, o);
    if (lane == 0) cost[n] = s;
}

// ----------------------------- launch ---------------------------------------
#define SINK_SMEM ((32*1024 + 1024 + 32) * 4 + 64)

extern "C" void kernel_launch(void* const* d_in, const int* in_sizes, int n_in,
                              void* d_out, int out_size) {
    const float* x  = (const float*)d_in[0];
    const float* y  = (const float*)d_in[1];
    const float* wx = (const float*)d_in[2];
    const float* wy = (const float*)d_in[3];

    float* out  = (float*)d_out;
    float* cost = out;                 // [4]
    float* pi   = out + NB;            // [4,1024,1024]
    float* C    = out + NB + PLANE;    // [4,1024,1024]

    cudaFuncSetAttribute(k_sink, cudaFuncAttributeMaxDynamicSharedMemorySize, SINK_SMEM);

    k_init<<<4, 1024>>>(wx, wy);
    dim3 gc(32, 32, 4);
    k_cost<<<gc, 256>>>(x, y, C);
    k_flags<<<1, 128>>>();
    k_sink<<<SBLOCKS, STHREADS, SINK_SMEM>>>(C, pi);
    k_final<<<1, 128>>>(cost);
}

// round 10
// speedup vs baseline: 1.5867x; 1.5867x over previous
#include <cuda_runtime.h>
#include <math.h>

// ---------------------------------------------------------------------------
// SinkhornDistance: N=4, P1=P2=1024, D=16, EPS=0.1, MAX_ITER=100, THRESH=0.1
// Outputs (concatenated fp32): cost[4], pi[4*1024*1024], C[4*1024*1024]
// Round 10: R8 leader 2-hop barrier restored (R9 poll storm reverted).
// BAR2 merged into gbarA entry; v-phase shares shv loads across its two
// columns with interleaved butterflies; publication on warp 15.
// ---------------------------------------------------------------------------

#define NB 4
#define P  1024
#define DD 16
#define EPSF 0.1f
#define KAP 14.426950408889634f        // log2(e)/eps
#define EPSLN2 0.06931471805599453f    // eps*ln2 = 1/KAP
#define MAX_ITER 100
#define THRESHF 0.1f
#define SBLOCKS 128
#define GBLK 32                        // blocks per batch group
#define STHREADS 512
#define PLANE (NB*P*P)

// ----------------------------- scratch (static device memory) ---------------
struct __align__(32) Flag { int v; int pad[7]; };
struct __align__(128) BigFlag { int v; int pad[31]; };
__device__ Flag     g_gflags[NB][GBLK];  // per-group arrival flags (32B apart)
__device__ BigFlag  g_ggo[NB];           // per-group go words (128B apart)
__device__ int      g_epoch[NB];         // last iteration published per group
__device__ float    g_errSum[NB][2];     // per-group err, ring by iter parity
__device__ float    g_CT[PLANE];         // transposed cost matrix (16 MB)
__device__ float    g_u[NB*P];           // kappa-scaled u
__device__ float    g_v[NB*P];           // kappa-scaled v
__device__ float    g_logmu[NB*P];
__device__ float    g_lognu[NB*P];
__device__ float    g_errPart[SBLOCKS];
__device__ float    g_rowPart[NB*P];

// ----------------------------- helpers --------------------------------------
__device__ __forceinline__ float ex2(float x) {
    float r; asm("ex2.approx.ftz.f32 %0, %1;" : "=f"(r) : "f"(x)); return r;
}
__device__ __forceinline__ float lg2(float x) {
    float r; asm("lg2.approx.ftz.f32 %0, %1;" : "=f"(r) : "f"(x)); return r;
}
__device__ __forceinline__ int ld_acq(const int* p) {
    int v; asm volatile("ld.acquire.gpu.s32 %0, [%1];" : "=r"(v) : "l"(p)); return v;
}
__device__ __forceinline__ void st_rel(int* p, int v) {
    asm volatile("st.release.gpu.s32 [%0], %1;" :: "l"(p), "r"(v));
}

// R8-style leader 2-hop group barrier (proven at 857us).
__device__ __forceinline__ void gbar(int n, int bb, int epoch) {
    __syncthreads();
    if (bb == 0) {
        if (threadIdx.x < 32) {
            int lane = threadIdx.x;
            if (lane == 0) st_rel(&g_gflags[n][0].v, epoch);
            bool ok;
            do { ok = ld_acq(&g_gflags[n][lane].v) >= epoch; }
            while (!__all_sync(0xffffffffu, ok));
            if (lane == 0) st_rel(&g_ggo[n].v, epoch);
        }
    } else if (threadIdx.x == 0) {
        st_rel(&g_gflags[n][bb].v, epoch);
        while (ld_acq(&g_ggo[n].v) < epoch) { }
    }
    __syncthreads();
}

// ----------------------------- kernel 0: init -------------------------------
__global__ void k_init(const float* __restrict__ wx, const float* __restrict__ wy) {
    int i = blockIdx.x * blockDim.x + threadIdx.x;   // 4096 threads total
    g_v[i] = 0.f;
    g_u[i] = 0.f;
    g_logmu[i] = logf(wx[i] + 1e-8f);
    g_lognu[i] = logf(wy[i] + 1e-8f);
}

// ----------------------------- kernel 1: cost matrix C and CT ---------------
__global__ void k_cost(const float* __restrict__ x, const float* __restrict__ y,
                       float* __restrict__ C) {
    __shared__ float xs[32][17];
    __shared__ float ys[32][17];
    __shared__ float tile[32][33];
    int n = blockIdx.z, I = blockIdx.y, J = blockIdx.x;
    int tid = threadIdx.x;   // 256

    for (int e = tid; e < 32 * DD; e += 256)
        xs[e >> 4][e & 15] = x[((size_t)(n * P + I * 32 + (e >> 4))) * DD + (e & 15)];
    for (int e = tid; e < 32 * DD; e += 256)
        ys[e >> 4][e & 15] = y[((size_t)(n * P + J * 32 + (e >> 4))) * DD + (e & 15)];
    __syncthreads();

    int ii = tid >> 3;
    int j0 = (tid & 7) * 4;
#pragma unroll
    for (int q = 0; q < 4; ++q) {
        int jj = j0 + q;
        float s = 0.f;
#pragma unroll
        for (int d = 0; d < DD; ++d) s += fabsf(xs[ii][d] - ys[jj][d]);
        tile[ii][jj] = s;
    }
    __syncthreads();

    for (int e = tid; e < 1024; e += 256) {
        int r = e >> 5, c = e & 31;
        C[((size_t)(n * P + I * 32 + r)) * P + (J * 32 + c)]    = tile[r][c];
        g_CT[((size_t)(n * P + J * 32 + r)) * P + (I * 32 + c)] = tile[c][r];
    }
}

// ----------------------------- kernel 2: barrier state reset ----------------
__global__ void k_flags() {
    int i = threadIdx.x;   // 128
    ((Flag*)g_gflags)[i].v = 0;
    if (i < NB) {
        g_ggo[i].v = 0;
        g_epoch[i] = -1;
    }
}

// ----------------------------- kernel 3: persistent Sinkhorn ----------------
// SMEM: tile[32][1024] (kappa*C rows) | shv[1024] staging | sdu[32]
__global__ void __launch_bounds__(STHREADS, 1)
k_sink(const float* __restrict__ C, float* __restrict__ pi) {
    extern __shared__ __align__(16) float smem[];
    float* tile = smem;                  // 32*1024
    float* shv  = smem + 32 * 1024;      // 1024 (kv, then ku)
    float* sdu  = shv + 1024;            // 32
    __shared__ int sdone;

    int tid = threadIdx.x;
    int w = tid >> 5, lane = tid & 31;   // 16 warps
    int b = blockIdx.x;
    int n = b >> 5, bb = b & 31;
    int r0 = (b << 5) + w;               // global rows of this warp
    int r1 = r0 + 16;
    int jc0 = (bb << 5) + w;             // columns of this warp (within batch)
    int jc1 = jc0 + 16;

    // ---- prologue: row tile (kappa*C), coalesced ----
    {
        const float4* src = (const float4*)(C + ((size_t)b << 15));
        float4* dst = (float4*)tile;
#pragma unroll
        for (int k = 0; k < 16; ++k) {
            float4 c = __ldcg(&src[tid + (k << 9)]);
            c.x *= KAP; c.y *= KAP; c.z *= KAP; c.w *= KAP;
            dst[tid + (k << 9)] = c;
        }
    }
    // ---- prologue: column registers (kappa*CT rows jc0, jc1), coalesced ----
    float ctreg[64];
    {
        const float* ct0 = g_CT + (((size_t)((n << 10) + jc0)) << 10);
        const float* ct1 = g_CT + (((size_t)((n << 10) + jc1)) << 10);
#pragma unroll
        for (int k = 0; k < 32; ++k) ctreg[k]      = __ldcg(&ct0[(k << 5) + lane]) * KAP;
#pragma unroll
        for (int k = 0; k < 32; ++k) ctreg[32 + k] = __ldcg(&ct1[(k << 5) + lane]) * KAP;
    }
    float lmu0 = g_logmu[r0], lmu1 = g_logmu[r1];
    float lnu0 = g_lognu[(n << 10) + jc0], lnu1 = g_lognu[(n << 10) + jc1];
    float up0 = 0.f, up1 = 0.f;          // previous raw u of own rows
    int ep = 1;
    __syncthreads();

    for (int it = 0; it < MAX_ITER; ++it) {
        // ---- stage kappa*v + lagged done check (warp0 lanes 0-3 parallel) ----
        shv[tid]       = __ldcg(&g_v[(n << 10) + tid]);
        shv[tid + 512] = __ldcg(&g_v[(n << 10) + tid + 512]);
        if (w == 0) {
            int d = 0;
            if (it > 0) {
                int need = it - 1;
                if (lane < 4) { while (ld_acq(&g_epoch[lane]) < need) { } }
                __syncwarp();
                float e = (lane < 4) ? __ldcg(&g_errSum[lane][need & 1]) : 0.f;
                e += __shfl_xor_sync(0xffffffffu, e, 1);
                e += __shfl_xor_sync(0xffffffffu, e, 2);
                e = __shfl_sync(0xffffffffu, e, 0);
                d = (e * 0.25f < THRESHF) ? 1 : 0;
            }
            if (lane == 0) sdone = d;
        }
        __syncthreads();                         // BAR1: shv + sdone
        if (sdone) break;

        // ---- u-phase: rows r0, r1 (tile rows w, w+16), as R8 ----
        {
            float u_new0, u_new1;
#pragma unroll
            for (int rr = 0; rr < 2; ++rr) {
                const float* trow = tile + (((rr << 4) + w) << 10);
                float t[16];
                float m1 = -3.0e38f;
#pragma unroll
                for (int k = 0; k < 4; ++k) {
                    int idx = (lane << 2) + (k << 7);
                    float4 c = *(const float4*)(trow + idx);
                    float4 v = *(const float4*)(shv + idx);
                    float a0 = v.x - c.x, a1 = v.y - c.y;
                    float a2 = v.z - c.z, a3 = v.w - c.w;
                    t[(k << 2) + 0] = a0; t[(k << 2) + 1] = a1;
                    t[(k << 2) + 2] = a2; t[(k << 2) + 3] = a3;
                    m1 = fmaxf(m1, fmaxf(fmaxf(a0, a1), fmaxf(a2, a3)));
                }
#pragma unroll
                for (int o = 16; o; o >>= 1) m1 = fmaxf(m1, __shfl_xor_sync(0xffffffffu, m1, o));
                float s1 = 0.f;
#pragma unroll
                for (int q = 0; q < 16; ++q) s1 += ex2(t[q] - m1);

                float m2 = -3.0e38f;
#pragma unroll
                for (int k = 4; k < 8; ++k) {
                    int idx = (lane << 2) + (k << 7);
                    float4 c = *(const float4*)(trow + idx);
                    float4 v = *(const float4*)(shv + idx);
                    float a0 = v.x - c.x, a1 = v.y - c.y;
                    float a2 = v.z - c.z, a3 = v.w - c.w;
                    t[((k - 4) << 2) + 0] = a0; t[((k - 4) << 2) + 1] = a1;
                    t[((k - 4) << 2) + 2] = a2; t[((k - 4) << 2) + 3] = a3;
                    m2 = fmaxf(m2, fmaxf(fmaxf(a0, a1), fmaxf(a2, a3)));
                }
#pragma unroll
                for (int o = 16; o; o >>= 1) m2 = fmaxf(m2, __shfl_xor_sync(0xffffffffu, m2, o));
                float s2 = 0.f;
#pragma unroll
                for (int q = 0; q < 16; ++q) s2 += ex2(t[q] - m2);

                float M = fmaxf(m1, m2);
                float S = s1 * ex2(m1 - M) + s2 * ex2(m2 - M);
#pragma unroll
                for (int o = 16; o; o >>= 1) S += __shfl_xor_sync(0xffffffffu, S, o);
                float L = M + lg2(S);

                float u_raw = EPSF * ((rr == 0) ? lmu0 : lmu1) - EPSLN2 * L;
                if (rr == 0) u_new0 = u_raw; else u_new1 = u_raw;
            }
            if (lane == 0) {
                sdu[w]      = fabsf(u_new0 - up0);
                sdu[w + 16] = fabsf(u_new1 - up1);
                __stcg(&g_u[r0], u_new0 * KAP);
                __stcg(&g_u[r1], u_new1 * KAP);
            }
            up0 = u_new0; up1 = u_new1;
        }

        // ---- merged BAR2 + gbarA: err reduce inside the barrier's warp0 ----
        __syncthreads();                         // covers sdu + g_u stores
        if (w == 0) {
            float e = sdu[lane];
#pragma unroll
            for (int o = 16; o; o >>= 1) e += __shfl_xor_sync(0xffffffffu, e, o);
            if (lane == 0) {
                __stcg(&g_errPart[b], e);
                st_rel(&g_gflags[n][bb].v, ep);  // release orders errPart + g_u
            }
            if (bb == 0) {
                bool ok;
                do { ok = ld_acq(&g_gflags[n][lane].v) >= ep; }
                while (!__all_sync(0xffffffffu, ok));
                if (lane == 0) st_rel(&g_ggo[n].v, ep);
            } else if (lane == 0) {
                while (ld_acq(&g_ggo[n].v) < ep) { }
            }
        }
        __syncthreads();
        ep++;

        // ---- err(it) + epoch published by warp 15 of group leader block ----
        if (bb == 0 && w == 15) {
            float e = __ldcg(&g_errPart[(n << 5) + lane]);
#pragma unroll
            for (int o = 16; o; o >>= 1) e += __shfl_xor_sync(0xffffffffu, e, o);
            if (lane == 0) {
                __stcg(&g_errSum[n][it & 1], e);
                st_rel(&g_epoch[n], it);
            }
        }

        // ---- stage kappa*u ----
        shv[tid]       = __ldcg(&g_u[(n << 10) + tid]);
        shv[tid + 512] = __ldcg(&g_u[(n << 10) + tid + 512]);
        __syncthreads();                         // BAR3: shv = kappa*u

        // ---- v-phase: both columns share shv loads, butterflies interleaved ----
        {
            float t0[16], t1[16];
            float m10 = -3.0e38f, m11 = -3.0e38f;
#pragma unroll
            for (int k = 0; k < 16; ++k) {
                float sv = shv[(k << 5) + lane];
                float a0 = sv - ctreg[k];
                float a1 = sv - ctreg[32 + k];
                t0[k] = a0; t1[k] = a1;
                m10 = fmaxf(m10, a0); m11 = fmaxf(m11, a1);
            }
#pragma unroll
            for (int o = 16; o; o >>= 1) {
                m10 = fmaxf(m10, __shfl_xor_sync(0xffffffffu, m10, o));
                m11 = fmaxf(m11, __shfl_xor_sync(0xffffffffu, m11, o));
            }
            float s10 = 0.f, s11 = 0.f;
#pragma unroll
            for (int q = 0; q < 16; ++q) {
                s10 += ex2(t0[q] - m10);
                s11 += ex2(t1[q] - m11);
            }

            float m20 = -3.0e38f, m21 = -3.0e38f;
#pragma unroll
            for (int k = 16; k < 32; ++k) {
                float sv = shv[(k << 5) + lane];
                float a0 = sv - ctreg[k];
                float a1 = sv - ctreg[32 + k];
                t0[k - 16] = a0; t1[k - 16] = a1;
                m20 = fmaxf(m20, a0); m21 = fmaxf(m21, a1);
            }
#pragma unroll
            for (int o = 16; o; o >>= 1) {
                m20 = fmaxf(m20, __shfl_xor_sync(0xffffffffu, m20, o));
                m21 = fmaxf(m21, __shfl_xor_sync(0xffffffffu, m21, o));
            }
            float s20 = 0.f, s21 = 0.f;
#pragma unroll
            for (int q = 0; q < 16; ++q) {
                s20 += ex2(t0[q] - m20);
                s21 += ex2(t1[q] - m21);
            }

            float M0 = fmaxf(m10, m20);
            float M1 = fmaxf(m11, m21);
            float S0 = s10 * ex2(m10 - M0) + s20 * ex2(m20 - M0);
            float S1 = s11 * ex2(m11 - M1) + s21 * ex2(m21 - M1);
#pragma unroll
            for (int o = 16; o; o >>= 1) {
                S0 += __shfl_xor_sync(0xffffffffu, S0, o);
                S1 += __shfl_xor_sync(0xffffffffu, S1, o);
            }
            float v0 = EPSF * lnu0 - EPSLN2 * (M0 + lg2(S0));
            float v1 = EPSF * lnu1 - EPSLN2 * (M1 + lg2(S1));
            if (lane == 0) {
                __stcg(&g_v[(n << 10) + jc0], v0 * KAP);
                __stcg(&g_v[(n << 10) + jc1], v1 * KAP);
            }
        }
        gbar(n, bb, ep++);                       // group: all g_v visible
    }

    // ---------------- epilogue: pi rows + per-row cost partial ----------------
    __syncthreads();
    shv[tid]       = __ldcg(&g_v[(n << 10) + tid]);        // kappa*v (fresh)
    shv[tid + 512] = __ldcg(&g_v[(n << 10) + tid + 512]);
    __syncthreads();
#pragma unroll
    for (int rr = 0; rr < 2; ++rr) {
        int rloc = (rr << 4) + w;
        int rg = (b << 5) + rloc;
        const float* trow = tile + (rloc << 10);
        float* prow = pi + ((size_t)rg << 10);
        float uk = ((rr == 0) ? up0 : up1) * KAP;
        float acc = 0.f;
#pragma unroll
        for (int k = 0; k < 8; ++k) {
            int idx = (lane << 2) + (k << 7);
            float4 c = *(const float4*)(trow + idx);
            float4 v = *(const float4*)(shv + idx);
            float4 p;
            p.x = ex2(uk + v.x - c.x);
            p.y = ex2(uk + v.y - c.y);
            p.z = ex2(uk + v.z - c.z);
            p.w = ex2(uk + v.w - c.w);
            __stcg((float4*)(prow + idx), p);
            acc += p.x * c.x + p.y * c.y + p.z * c.z + p.w * c.w;
        }
#pragma unroll
        for (int o = 16; o; o >>= 1) acc += __shfl_xor_sync(0xffffffffu, acc, o);
        if (lane == 0) __stcg(&g_rowPart[rg], acc * EPSLN2);   // undo kappa on C
    }
}

// ----------------------------- kernel 4: deterministic cost reduce ----------
__global__ void k_final(float* __restrict__ cost) {
    int tid = threadIdx.x;   // 128
    int n = tid >> 5, lane = tid & 31;
    float s = 0.f;
#pragma unroll
    for (int q = 0; q < 32; ++q) s += g_rowPart[(n << 10) + lane + (q << 5)];
#pragma unroll
    for (int o = 16; o; o >>= 1) s += __shfl_xor_sync(0xffffffffu, s, o);
    if (lane == 0) cost[n] = s;
}

// ----------------------------- launch ---------------------------------------
#define SINK_SMEM ((32*1024 + 1024 + 32) * 4 + 64)

extern "C" void kernel_launch(void* const* d_in, const int* in_sizes, int n_in,
                              void* d_out, int out_size) {
    const float* x  = (const float*)d_in[0];
    const float* y  = (const float*)d_in[1];
    const float* wx = (const float*)d_in[2];
    const float* wy = (const float*)d_in[3];

    float* out  = (float*)d_out;
    float* cost = out;                 // [4]
    float* pi   = out + NB;            // [4,1024,1024]
    float* C    = out + NB + PLANE;    // [4,1024,1024]

    cudaFuncSetAttribute(k_sink, cudaFuncAttributeMaxDynamicSharedMemorySize, SINK_SMEM);

    k_init<<<4, 1024>>>(wx, wy);
    dim3 gc(32, 32, 4);
    k_cost<<<gc, 256>>>(x, y, C);
    k_flags<<<1, 128>>>();
    k_sink<<<SBLOCKS, STHREADS, SINK_SMEM>>>(C, pi);
    k_final<<<1, 128>>>(cost);
}